// round 7
// baseline (speedup 1.0000x reference)
#include <cuda_runtime.h>
#include <cuda_bf16.h>
#include <cstdint>
#include <math.h>

#define NN 10000
#define EE 160000
#define ET (EE + NN)
#define HH 8
#define DD 128
#define HD 1024   // H*D

// ---------------- scratch (static device allocations; no cudaMalloc) --------
__device__ int   d_is64;
__device__ int   d_deg[NN];
__device__ int   d_cursor[NN];
__device__ int   d_rowptr[NN + 1];
__device__ int   d_colsrc[ET];
__device__ __align__(16) float d_as[NN * HH];
__device__ __align__(16) float d_ad[NN * HH];
__device__ __align__(16) float d_dinv[NN];
__device__ __align__(16) float d_snode[NN * 32];   // [N][H][4]
__device__ __align__(16) float d_t1[NN * DD];
__device__ __align__(16) float d_h1[NN * DD];
__device__ __align__(16) float d_t2[NN * DD];
__device__ __align__(16) float d_csrc[32];         // [H][4]
__device__ __align__(16) float d_cdst[32];

// ---------------- helpers ---------------------------------------------------
__device__ __forceinline__ float gelu_exact(float v) {
    return 0.5f * v * (1.0f + erff(v * 0.70710678118654752440f));
}

__device__ __forceinline__ unsigned long long fma2(unsigned long long a,
                                                   unsigned long long b,
                                                   unsigned long long c) {
    unsigned long long d;
    asm("fma.rn.f32x2 %0, %1, %2, %3;" : "=l"(d) : "l"(a), "l"(b), "l"(c));
    return d;
}
__device__ __forceinline__ unsigned long long pack2(float x, float y) {
    unsigned long long r;
    asm("mov.b64 %0, {%1, %2};" : "=l"(r) : "f"(x), "f"(y));
    return r;
}
__device__ __forceinline__ void unpack2(unsigned long long v, float& x, float& y) {
    asm("mov.b64 {%0, %1}, %2;" : "=f"(x), "=f"(y) : "l"(v));
}

// ---------------- dtype detection for edge_index ----------------------------
// int64 little-endian values < 2^31 have all-zero odd 32-bit words.
__global__ void k_detect(const int* __restrict__ w) {
    __shared__ int nz;
    if (threadIdx.x == 0) nz = 0;
    __syncthreads();
    if (w[2 * threadIdx.x + 1] != 0) atomicOr(&nz, 1);
    __syncthreads();
    if (threadIdx.x == 0) d_is64 = nz ? 0 : 1;
}

// ---------------- prep: c_src/c_dst = gat_w^T @ att (rank-4 collapse) -------
__global__ void k_prep_c(const float* __restrict__ gw,
                         const float* __restrict__ asrc,
                         const float* __restrict__ adst) {
    int t = threadIdx.x;
    if (t >= 64) return;
    int which = t >> 5;            // 0: src, 1: dst
    int idx = t & 31;              // h*4+f
    int h = idx >> 2, f = idx & 3;
    const float* att = which ? adst : asrc;
    float s = 0.0f;
    for (int d = 0; d < DD; d++)
        s += gw[f * HD + h * DD + d] * att[h * DD + d];
    if (which) d_cdst[idx] = s; else d_csrc[idx] = s;
}

// ---------------- CSR build -------------------------------------------------
__global__ void k_init() {
    int i = blockIdx.x * blockDim.x + threadIdx.x;
    if (i < NN) { d_deg[i] = 1; d_cursor[i] = 0; }   // deg starts at 1 (self loop)
}

__global__ void k_count(const int* __restrict__ w) {
    int e = blockIdx.x * blockDim.x + threadIdx.x;
    if (e >= EE) return;
    int is64 = d_is64;
    int dd = is64 ? w[2 * (EE + e)] : w[EE + e];
    if ((unsigned)dd < NN) atomicAdd(&d_deg[dd], 1);
}

__global__ void k_scan() {   // 1 block, 1024 threads
    __shared__ int sh[1024];
    int t = threadIdx.x;
    const int C = 10;                 // 1024*10 >= 10000
    int base = t * C;
    int sum = 0;
    for (int i = 0; i < C; i++) {
        int idx = base + i;
        if (idx < NN) sum += d_deg[idx];
    }
    sh[t] = sum;
    __syncthreads();
    for (int off = 1; off < 1024; off <<= 1) {
        int v = 0;
        if (t >= off) v = sh[t - off];
        __syncthreads();
        if (t >= off) sh[t] += v;
        __syncthreads();
    }
    int run = sh[t] - sum;            // exclusive prefix
    for (int i = 0; i < C; i++) {
        int idx = base + i;
        if (idx < NN) { d_rowptr[idx] = run; run += d_deg[idx]; }
    }
    if (t == 1023) d_rowptr[NN] = sh[1023];
}

__global__ void k_fill(const int* __restrict__ w) {
    int t = blockIdx.x * blockDim.x + threadIdx.x;
    if (t >= ET) return;
    int is64 = d_is64;
    int s, dd;
    if (t < EE) {
        s  = is64 ? w[2 * t]        : w[t];
        dd = is64 ? w[2 * (EE + t)] : w[EE + t];
    } else {
        s = t - EE; dd = s;           // self loop
    }
    if ((unsigned)dd >= NN || (unsigned)s >= NN) return;
    int pos = atomicAdd(&d_cursor[dd], 1);
    d_colsrc[d_rowptr[dd] + pos] = s;
}

// ---------------- per-node: attention scores + dinv -------------------------
__global__ void k_node(const float* __restrict__ x) {
    int n = blockIdx.x * blockDim.x + threadIdx.x;
    if (n >= NN) return;
    float4 xv = ((const float4*)x)[n];
#pragma unroll
    for (int h = 0; h < HH; h++) {
        d_as[n * 8 + h] = xv.x * d_csrc[h * 4 + 0] + xv.y * d_csrc[h * 4 + 1]
                        + xv.z * d_csrc[h * 4 + 2] + xv.w * d_csrc[h * 4 + 3];
        d_ad[n * 8 + h] = xv.x * d_cdst[h * 4 + 0] + xv.y * d_cdst[h * 4 + 1]
                        + xv.z * d_cdst[h * 4 + 2] + xv.w * d_cdst[h * 4 + 3];
    }
    d_dinv[n] = rsqrtf((float)d_deg[n]);
}

// ---------------- GAT: ONE-PASS online softmax + rank-4 aggregation ---------
__global__ void k_gat(const float* __restrict__ x) {
    int node = blockIdx.x * 32 + (threadIdx.x >> 3);   // 32 nodes per block
    int h = threadIdx.x & 7;
    if (node >= NN) return;
    int r0 = d_rowptr[node], r1 = d_rowptr[node + 1];
    float ad = d_ad[node * 8 + h];
    float m = -1e30f, den = 0.0f;
    float t0 = 0.0f, t1 = 0.0f, t2 = 0.0f, t3 = 0.0f;
    for (int i = r0; i < r1; i++) {
        int s = d_colsrc[i];
        float e = d_as[s * 8 + h] + ad;
        e = e > 0.0f ? e : 0.2f * e;
        float ex;
        if (e > m) {
            float sc = expf(m - e);       // first iter: expf(-huge) = 0
            den *= sc; t0 *= sc; t1 *= sc; t2 *= sc; t3 *= sc;
            m = e;
            ex = 1.0f;
        } else {
            ex = expf(e - m);
        }
        float4 xv = ((const float4*)x)[s];
        den += ex;
        t0 += ex * xv.x; t1 += ex * xv.y; t2 += ex * xv.z; t3 += ex * xv.w;
    }
    float inv = 1.0f / den;
    float* sp = &d_snode[node * 32 + h * 4];
    sp[0] = t0 * inv; sp[1] = t1 * inv; sp[2] = t2 * inv; sp[3] = t3 * inv;
}

// ---------------- fused GEMM1: t1 = gelu(S@gat_w + gb) @ w1 ------------------
// A tile (64 x 16) generated in-kernel from S (rank-32), double-prefetch of
// B tile rows and gw/gb columns into registers; single smem buffer.
// BM=64, BN=128 (full), BK=16, 256 threads, TM=8 x TN=4 as f32x2 pairs.
#define ROWFMA(r, ax) { unsigned long long _ad = pack2((ax), (ax)); \
    acc[r][0] = fma2(_ad, b01, acc[r][0]); acc[r][1] = fma2(_ad, b23, acc[r][1]); }

__global__ __launch_bounds__(256, 2) void k_fgemm1(const float* __restrict__ B,
                                                   const float* __restrict__ gw,
                                                   const float* __restrict__ gb,
                                                   int M) {
    __shared__ float Ssh[64 * 36];     // padded rank-32 rows
    __shared__ float As[16][64];
    __shared__ float Bs[16][128];

    int t = threadIdx.x;
    int bm = blockIdx.x * 64;

    // load S rows for this tile (pad rows >= M with 0)
    for (int idx = t; idx < 512; idx += 256) {
        int row = idx >> 3, q = idx & 7;
        int g = bm + row;
        float4 v = (g < M) ? ((const float4*)d_snode)[g * 8 + q]
                           : make_float4(0.f, 0.f, 0.f, 0.f);
        *(float4*)&Ssh[row * 36 + q * 4] = v;
    }
    __syncthreads();                   // Ssh visible before any A-gen read (race fix)

    int arow = t >> 2;                // A-gen: 64 rows x 4 cols per thread
    int acol = (t & 3) * 4;
    int brow = t >> 5;                // B tile: rows brow, brow+8
    int bcol = (t & 31) * 4;
    int row0 = (t >> 5) * 8;          // mainloop: 8 rows per thread
    int col0 = (t & 31) * 4;          // 4 cols per thread

    // prologue prefetch for kt = 0
    float4 bReg0 = *(const float4*)(B + brow * 128 + bcol);
    float4 bReg1 = *(const float4*)(B + (brow + 8) * 128 + bcol);
    int j0 = acol;                    // global col of this thread's A strip
    float4 gw0 = *(const float4*)(gw + j0);
    float4 gw1 = *(const float4*)(gw + HD + j0);
    float4 gw2 = *(const float4*)(gw + 2 * HD + j0);
    float4 gw3 = *(const float4*)(gw + 3 * HD + j0);
    float4 gbv = *(const float4*)(gb + j0);

    unsigned long long acc[8][2];
#pragma unroll
    for (int r = 0; r < 8; r++) { acc[r][0] = 0ULL; acc[r][1] = 0ULL; }

    for (int kt = 0; kt < 64; kt++) {
        if (kt > 0) __syncthreads();          // mainloop(kt-1) finished reading

        // stage B tile
        *(float4*)&Bs[brow][bcol] = bReg0;
        *(float4*)&Bs[brow + 8][bcol] = bReg1;

        // generate A tile: A[arow][acol..+3] = gelu(gb + S . gw)
        {
            int head = kt >> 3;
            float4 sp = *(const float4*)&Ssh[arow * 36 + head * 4];
            float v0 = gbv.x + sp.x * gw0.x + sp.y * gw1.x + sp.z * gw2.x + sp.w * gw3.x;
            float v1 = gbv.y + sp.x * gw0.y + sp.y * gw1.y + sp.z * gw2.y + sp.w * gw3.y;
            float v2 = gbv.z + sp.x * gw0.z + sp.y * gw1.z + sp.z * gw2.z + sp.w * gw3.z;
            float v3 = gbv.w + sp.x * gw0.w + sp.y * gw1.w + sp.z * gw2.w + sp.w * gw3.w;
            As[acol + 0][arow] = gelu_exact(v0);
            As[acol + 1][arow] = gelu_exact(v1);
            As[acol + 2][arow] = gelu_exact(v2);
            As[acol + 3][arow] = gelu_exact(v3);
        }
        __syncthreads();

        // prefetch next step's B rows and gw/gb strip (overlaps mainloop)
        if (kt + 1 < 64) {
            int k0 = (kt + 1) * 16;
            bReg0 = *(const float4*)(B + (k0 + brow) * 128 + bcol);
            bReg1 = *(const float4*)(B + (k0 + brow + 8) * 128 + bcol);
            int j = k0 + acol;
            gw0 = *(const float4*)(gw + j);
            gw1 = *(const float4*)(gw + HD + j);
            gw2 = *(const float4*)(gw + 2 * HD + j);
            gw3 = *(const float4*)(gw + 3 * HD + j);
            gbv = *(const float4*)(gb + j);
        }

#pragma unroll
        for (int k = 0; k < 16; k++) {
            float4 a0 = *(const float4*)&As[k][row0];
            float4 a1 = *(const float4*)&As[k][row0 + 4];
            float4 bv = *(const float4*)&Bs[k][col0];
            unsigned long long b01 = pack2(bv.x, bv.y);
            unsigned long long b23 = pack2(bv.z, bv.w);
            ROWFMA(0, a0.x) ROWFMA(1, a0.y) ROWFMA(2, a0.z) ROWFMA(3, a0.w)
            ROWFMA(4, a1.x) ROWFMA(5, a1.y) ROWFMA(6, a1.z) ROWFMA(7, a1.w)
        }
    }

#pragma unroll
    for (int r = 0; r < 8; r++) {
        int m = bm + row0 + r;
        if (m < M) {
            float4 o;
            unpack2(acc[r][0], o.x, o.y);
            unpack2(acc[r][1], o.z, o.w);
            *(float4*)&d_t1[m * 128 + col0] = o;
        }
    }
}

// ---------------- GEMM2: t2 = h1[M,128] @ w2^... (B = w2 [128][128]) --------
// round-2 gemm body, K=128, A=d_h1, C=d_t2, double-buffered smem.
__global__ __launch_bounds__(256, 2) void gemm2_kernel(const float* __restrict__ B, int M) {
    const float* A = d_h1;
    float* C       = d_t2;
    const int K = 128;

    __shared__ float As[2][16][64];
    __shared__ float Bs[2][16][128];

    int t = threadIdx.x;
    int bm = blockIdx.x * 64;
    int row0 = (t >> 5) * 8;
    int col0 = (t & 31) * 4;

    int arow = t >> 2;
    int acol = (t & 3) * 4;
    int brow = t >> 5;
    int bcol = (t & 31) * 4;

    const int nk = K / 16;
    float4 aReg, bReg0, bReg1;

    {
        int m = bm + arow;
        aReg = (m < M) ? *(const float4*)(A + (size_t)m * K + acol)
                       : make_float4(0.f, 0.f, 0.f, 0.f);
        bReg0 = *(const float4*)(B + brow * 128 + bcol);
        bReg1 = *(const float4*)(B + (brow + 8) * 128 + bcol);
        As[0][acol + 0][arow] = aReg.x;
        As[0][acol + 1][arow] = aReg.y;
        As[0][acol + 2][arow] = aReg.z;
        As[0][acol + 3][arow] = aReg.w;
        *(float4*)&Bs[0][brow][bcol] = bReg0;
        *(float4*)&Bs[0][brow + 8][bcol] = bReg1;
    }
    __syncthreads();

    unsigned long long acc[8][2];
#pragma unroll
    for (int r = 0; r < 8; r++) { acc[r][0] = 0ULL; acc[r][1] = 0ULL; }

    for (int kt = 0; kt < nk; kt++) {
        int cur = kt & 1;
        if (kt + 1 < nk) {
            int k0 = (kt + 1) * 16;
            int m = bm + arow;
            aReg = (m < M) ? *(const float4*)(A + (size_t)m * K + k0 + acol)
                           : make_float4(0.f, 0.f, 0.f, 0.f);
            bReg0 = *(const float4*)(B + (k0 + brow) * 128 + bcol);
            bReg1 = *(const float4*)(B + (k0 + brow + 8) * 128 + bcol);
        }
#pragma unroll
        for (int k = 0; k < 16; k++) {
            float4 a0 = *(const float4*)&As[cur][k][row0];
            float4 a1 = *(const float4*)&As[cur][k][row0 + 4];
            float4 bv = *(const float4*)&Bs[cur][k][col0];
            unsigned long long b01 = pack2(bv.x, bv.y);
            unsigned long long b23 = pack2(bv.z, bv.w);
            ROWFMA(0, a0.x) ROWFMA(1, a0.y) ROWFMA(2, a0.z) ROWFMA(3, a0.w)
            ROWFMA(4, a1.x) ROWFMA(5, a1.y) ROWFMA(6, a1.z) ROWFMA(7, a1.w)
        }
        if (kt + 1 < nk) {
            int nxt = cur ^ 1;
            As[nxt][acol + 0][arow] = aReg.x;
            As[nxt][acol + 1][arow] = aReg.y;
            As[nxt][acol + 2][arow] = aReg.z;
            As[nxt][acol + 3][arow] = aReg.w;
            *(float4*)&Bs[nxt][brow][bcol] = bReg0;
            *(float4*)&Bs[nxt][brow + 8][bcol] = bReg1;
            __syncthreads();
        }
    }

#pragma unroll
    for (int r = 0; r < 8; r++) {
        int m = bm + row0 + r;
        if (m < M) {
            float4 o;
            unpack2(acc[r][0], o.x, o.y);
            unpack2(acc[r][1], o.z, o.w);
            *(float4*)&C[m * 128 + col0] = o;
        }
    }
}

// ---------------- GCN aggregation: out[n] = (opt gelu)(dinv[n]*S dinv[s]*t[s] + b)
template <bool GELU, bool FIRST>
__global__ void k_agg(const float* __restrict__ bias, float* __restrict__ ext_out) {
    const float* tin = FIRST ? d_t1 : d_t2;
    float*       outp = FIRST ? d_h1 : ext_out;
    int node = blockIdx.x * 8 + (threadIdx.x >> 5);
    int lane = threadIdx.x & 31;
    if (node >= NN) return;
    int r0 = d_rowptr[node], r1 = d_rowptr[node + 1];
    float4 acc = make_float4(0.f, 0.f, 0.f, 0.f);
    const float4* t4 = (const float4*)tin;
    for (int i = r0; i < r1; i++) {
        int s = d_colsrc[i];
        float w = d_dinv[s];
        float4 v = t4[s * 32 + lane];
        acc.x += w * v.x; acc.y += w * v.y; acc.z += w * v.z; acc.w += w * v.w;
    }
    float dn = d_dinv[node];
    float4 b = ((const float4*)bias)[lane];
    float4 r;
    r.x = acc.x * dn + b.x;
    r.y = acc.y * dn + b.y;
    r.z = acc.z * dn + b.z;
    r.w = acc.w * dn + b.w;
    if (GELU) {
        r.x = gelu_exact(r.x); r.y = gelu_exact(r.y);
        r.z = gelu_exact(r.z); r.w = gelu_exact(r.w);
    }
    ((float4*)outp)[node * 32 + lane] = r;
}

// ---------------- launch -----------------------------------------------------
extern "C" void kernel_launch(void* const* d_in, const int* in_sizes, int n_in,
                              void* d_out, int out_size) {
    const float* x       = (const float*)d_in[0];
    const int*   eiw     = (const int*)d_in[1];      // words; dtype detected on device
    const float* gat_w   = (const float*)d_in[2];
    const float* att_src = (const float*)d_in[3];
    const float* att_dst = (const float*)d_in[4];
    const float* gat_b   = (const float*)d_in[5];
    const float* w1      = (const float*)d_in[6];
    const float* b1      = (const float*)d_in[7];
    const float* w2      = (const float*)d_in[8];
    const float* b2      = (const float*)d_in[9];
    float* out = (float*)d_out;

    k_detect<<<1, 128>>>(eiw);
    k_prep_c<<<1, 64>>>(gat_w, att_src, att_dst);
    k_init<<<(NN + 255) / 256, 256>>>();
    k_count<<<(EE + 255) / 256, 256>>>(eiw);
    k_scan<<<1, 1024>>>();
    k_fill<<<(ET + 255) / 256, 256>>>(eiw);
    k_node<<<(NN + 255) / 256, 256>>>(x);
    k_gat<<<(NN + 31) / 32, 256>>>(x);
    k_fgemm1<<<(NN + 63) / 64, 256>>>(w1, gat_w, gat_b, NN);
    k_agg<true, true><<<(NN + 7) / 8, 256>>>(b1, nullptr);
    gemm2_kernel<<<(NN + 63) / 64, 256>>>(w2, NN);
    k_agg<false, false><<<(NN + 7) / 8, 256>>>(b2, out);
}

// round 9
// speedup vs baseline: 1.2062x; 1.2062x over previous
#include <cuda_runtime.h>
#include <cuda_bf16.h>
#include <cstdint>
#include <math.h>

#define NN 10000
#define EE 160000
#define ET (EE + NN)
#define HH 8
#define DD 128
#define HD 1024   // H*D

// ---------------- scratch (static device allocations; no cudaMalloc) --------
__device__ int   d_is64;
__device__ int   d_deg[NN];
__device__ int   d_cursor[NN];
__device__ int   d_rowptr[NN + 1];
__device__ int   d_colsrc[ET];
__device__ __align__(16) float d_as[NN * HH];
__device__ __align__(16) float d_ad[NN * HH];
__device__ __align__(16) float d_dinv[NN];
__device__ __align__(16) float d_snode[NN * 32];   // [N][H][4]
__device__ __align__(16) float d_t1[NN * DD];
__device__ __align__(16) float d_t2[NN * DD];
__device__ __align__(16) __nv_bfloat16 d_h1hi[NN * DD];
__device__ __align__(16) __nv_bfloat16 d_h1lo[NN * DD];
__device__ __align__(16) __nv_bfloat16 d_b1hi[DD * HD];  // w1^T split [128][1024]
__device__ __align__(16) __nv_bfloat16 d_b1lo[DD * HD];
__device__ __align__(16) __nv_bfloat16 d_b2hi[DD * DD];  // w2^T split [128][128]
__device__ __align__(16) __nv_bfloat16 d_b2lo[DD * DD];
__device__ __align__(16) float d_csrc[32];         // [H][4]
__device__ __align__(16) float d_cdst[32];

// ---------------- helpers ---------------------------------------------------
__device__ __forceinline__ float gelu_exact(float v) {
    return 0.5f * v * (1.0f + erff(v * 0.70710678118654752440f));
}

__device__ __forceinline__ void ldsm4(uint32_t* r, uint32_t addr) {
    asm volatile("ldmatrix.sync.aligned.m8n8.x4.shared.b16 {%0,%1,%2,%3}, [%4];"
                 : "=r"(r[0]), "=r"(r[1]), "=r"(r[2]), "=r"(r[3]) : "r"(addr));
}
__device__ __forceinline__ void ldsm2(uint32_t* r, uint32_t addr) {
    asm volatile("ldmatrix.sync.aligned.m8n8.x2.shared.b16 {%0,%1}, [%2];"
                 : "=r"(r[0]), "=r"(r[1]) : "r"(addr));
}
__device__ __forceinline__ void mma_bf16(float* c, const uint32_t* a, const uint32_t* b) {
    asm volatile("mma.sync.aligned.m16n8k16.row.col.f32.bf16.bf16.f32 "
                 "{%0,%1,%2,%3}, {%4,%5,%6,%7}, {%8,%9}, {%0,%1,%2,%3};"
                 : "+f"(c[0]), "+f"(c[1]), "+f"(c[2]), "+f"(c[3])
                 : "r"(a[0]), "r"(a[1]), "r"(a[2]), "r"(a[3]), "r"(b[0]), "r"(b[1]));
}
__device__ __forceinline__ void cp16(void* dst, const void* src) {
    uint32_t d = (uint32_t)__cvta_generic_to_shared(dst);
    asm volatile("cp.async.ca.shared.global [%0], [%1], 16;" :: "r"(d), "l"(src) : "memory");
}

// ---------------- setup: dtype detect + prep_c + deg init -------------------
__global__ void k_setup(const int* __restrict__ w,
                        const float* __restrict__ gw,
                        const float* __restrict__ asrc,
                        const float* __restrict__ adst) {
    int i = blockIdx.x * blockDim.x + threadIdx.x;
    if (i < NN) { d_deg[i] = 1; d_cursor[i] = 0; }
    if (blockIdx.x == 0) {
        __shared__ int nz;
        if (threadIdx.x == 0) nz = 0;
        __syncthreads();
        if (threadIdx.x < 128 && w[2 * threadIdx.x + 1] != 0) atomicOr(&nz, 1);
        __syncthreads();
        if (threadIdx.x == 0) d_is64 = nz ? 0 : 1;
        int t = threadIdx.x;
        if (t < 64) {
            int which = t >> 5;
            int idx = t & 31;
            int h = idx >> 2, f = idx & 3;
            const float* att = which ? adst : asrc;
            float s = 0.0f;
            for (int d = 0; d < DD; d++)
                s += gw[f * HD + h * DD + d] * att[h * DD + d];
            if (which) d_cdst[idx] = s; else d_csrc[idx] = s;
        }
    }
}

// ---------------- B prep: transpose + bf16 split (w1 and w2 in one) ---------
__global__ void k_prepB(const float* __restrict__ w1, const float* __restrict__ w2) {
    int idx = blockIdx.x * blockDim.x + threadIdx.x;
    if (idx < 128 * HD) {
        int n = idx >> 10, k = idx & (HD - 1);
        float v = w1[k * 128 + n];
        __nv_bfloat16 h = __float2bfloat16(v);
        d_b1hi[idx] = h;
        d_b1lo[idx] = __float2bfloat16(v - __bfloat162float(h));
    } else {
        int r = idx - 128 * HD;
        if (r < 128 * 128) {
            int n = r >> 7, k = r & 127;
            float v = w2[k * 128 + n];
            __nv_bfloat16 h = __float2bfloat16(v);
            d_b2hi[r] = h;
            d_b2lo[r] = __float2bfloat16(v - __bfloat162float(h));
        }
    }
}

// ---------------- CSR build -------------------------------------------------
__global__ void k_count(const int* __restrict__ w) {
    int e = blockIdx.x * blockDim.x + threadIdx.x;
    if (e >= EE) return;
    int is64 = d_is64;
    int dd = is64 ? w[2 * (EE + e)] : w[EE + e];
    if ((unsigned)dd < NN) atomicAdd(&d_deg[dd], 1);
}

__global__ void k_scan() {   // 1 block, 1024 threads
    __shared__ int sh[1024];
    int t = threadIdx.x;
    const int C = 10;
    int base = t * C;
    int sum = 0;
    for (int i = 0; i < C; i++) {
        int idx = base + i;
        if (idx < NN) sum += d_deg[idx];
    }
    sh[t] = sum;
    __syncthreads();
    for (int off = 1; off < 1024; off <<= 1) {
        int v = 0;
        if (t >= off) v = sh[t - off];
        __syncthreads();
        if (t >= off) sh[t] += v;
        __syncthreads();
    }
    int run = sh[t] - sum;
    for (int i = 0; i < C; i++) {
        int idx = base + i;
        if (idx < NN) { d_rowptr[idx] = run; run += d_deg[idx]; }
    }
    if (t == 1023) d_rowptr[NN] = sh[1023];
}

// ---------------- fill CSR + per-node scores/dinv (merged) ------------------
__global__ void k_fillnode(const int* __restrict__ w, const float* __restrict__ x) {
    int t = blockIdx.x * blockDim.x + threadIdx.x;
    if (t < NN) {
        float4 xv = ((const float4*)x)[t];
#pragma unroll
        for (int h = 0; h < HH; h++) {
            d_as[t * 8 + h] = xv.x * d_csrc[h * 4 + 0] + xv.y * d_csrc[h * 4 + 1]
                            + xv.z * d_csrc[h * 4 + 2] + xv.w * d_csrc[h * 4 + 3];
            d_ad[t * 8 + h] = xv.x * d_cdst[h * 4 + 0] + xv.y * d_cdst[h * 4 + 1]
                            + xv.z * d_cdst[h * 4 + 2] + xv.w * d_cdst[h * 4 + 3];
        }
        d_dinv[t] = rsqrtf((float)d_deg[t]);
    }
    if (t >= ET) return;
    int is64 = d_is64;
    int s, dd;
    if (t < EE) {
        s  = is64 ? w[2 * t]        : w[t];
        dd = is64 ? w[2 * (EE + t)] : w[EE + t];
    } else {
        s = t - EE; dd = s;           // self loop
    }
    if ((unsigned)dd >= NN || (unsigned)s >= NN) return;
    int pos = atomicAdd(&d_cursor[dd], 1);
    d_colsrc[d_rowptr[dd] + pos] = s;
}

// ---------------- GAT: one-pass online softmax + rank-4 aggregation ---------
__global__ void k_gat(const float* __restrict__ x) {
    int node = blockIdx.x * 32 + (threadIdx.x >> 3);
    int h = threadIdx.x & 7;
    if (node >= NN) return;
    int r0 = d_rowptr[node], r1 = d_rowptr[node + 1];
    float ad = d_ad[node * 8 + h];
    float m = -1e30f, den = 0.0f;
    float t0 = 0.0f, t1 = 0.0f, t2 = 0.0f, t3 = 0.0f;
    for (int i = r0; i < r1; i++) {
        int s = d_colsrc[i];
        float e = d_as[s * 8 + h] + ad;
        e = e > 0.0f ? e : 0.2f * e;
        float ex;
        if (e > m) {
            float sc = expf(m - e);
            den *= sc; t0 *= sc; t1 *= sc; t2 *= sc; t3 *= sc;
            m = e;
            ex = 1.0f;
        } else {
            ex = expf(e - m);
        }
        float4 xv = ((const float4*)x)[s];
        den += ex;
        t0 += ex * xv.x; t1 += ex * xv.y; t2 += ex * xv.z; t3 += ex * xv.w;
    }
    float inv = 1.0f / den;
    float* sp = &d_snode[node * 32 + h * 4];
    sp[0] = t0 * inv; sp[1] = t1 * inv; sp[2] = t2 * inv; sp[3] = t3 * inv;
}

// ---------------- split-bf16 mma.sync GEMM ----------------------------------
// C[M,128] = A[M,K] @ W[K,128] using m16n8k16 bf16 mma, fp32 acc.
// A hi/lo: which=0 -> generated in-kernel from S (gelu(S@gw+gb)); which=1 -> d_h1hi/lo.
// B hi/lo: d_b1*/d_b2* as [128][K] (=W^T, k contiguous).
// BM=64, 128 threads (4 warps), warp tile 16x128; BK=16, cp.async double buffer.
// Stage layout (bytes): Ah[2 planes][64][16B] @0 (2KB), Al @2048,
//                       Bh[128][48B] @4096 (6KB), Bl @10240.  Stage = 16KB.
#define OFF_AH 0
#define OFF_AL 2048
#define OFF_BH 4096
#define OFF_BL 10240
#define STAGE_BYTES 16384

__device__ __forceinline__ void gen_a(char* stg, const float* Ssh,
                                      const float* __restrict__ gw,
                                      const float* __restrict__ gb,
                                      int k0, int t) {
    int m = t >> 1, half = t & 1;
    const float* sp = Ssh + m * 36 + ((k0 >> 7) << 2);
    float s0 = sp[0], s1 = sp[1], s2 = sp[2], s3 = sp[3];
    int jb = k0 + half * 8;
    uint32_t hi4[4], lo4[4];
#pragma unroll
    for (int q = 0; q < 4; q++) {
        uint32_t hh = 0, ll = 0;
#pragma unroll
        for (int u = 0; u < 2; u++) {
            int j = jb + q * 2 + u;
            float a = __ldg(gb + j) + s0 * __ldg(gw + j) + s1 * __ldg(gw + HD + j)
                    + s2 * __ldg(gw + 2 * HD + j) + s3 * __ldg(gw + 3 * HD + j);
            float v = gelu_exact(a);
            __nv_bfloat16 h = __float2bfloat16(v);
            __nv_bfloat16 l = __float2bfloat16(v - __bfloat162float(h));
            hh |= (uint32_t)__bfloat16_as_ushort(h) << (u * 16);
            ll |= (uint32_t)__bfloat16_as_ushort(l) << (u * 16);
        }
        hi4[q] = hh; lo4[q] = ll;
    }
    *(uint4*)(stg + OFF_AH + half * 1024 + m * 16) = make_uint4(hi4[0], hi4[1], hi4[2], hi4[3]);
    *(uint4*)(stg + OFF_AL + half * 1024 + m * 16) = make_uint4(lo4[0], lo4[1], lo4[2], lo4[3]);
}

__device__ __forceinline__ void load_b(char* stg, const __nv_bfloat16* gBhi,
                                       const __nv_bfloat16* gBlo, int K, int k0, int t) {
#pragma unroll
    for (int i = 0; i < 4; i++) {
        int idx = t + i * 128;          // 0..511
        int hilo = idx >> 8;
        int r = idx & 255;
        int n = r >> 1, half = r & 1;
        char* dst = stg + (hilo ? OFF_BL : OFF_BH) + n * 48 + half * 16;
        const __nv_bfloat16* src = (hilo ? gBlo : gBhi) + (size_t)n * K + k0 + half * 8;
        cp16(dst, src);
    }
}

__device__ __forceinline__ void load_a(char* stg, int K, int k0, int t, int bm, int M) {
#pragma unroll
    for (int i = 0; i < 2; i++) {
        int idx = t + i * 128;          // 0..255
        int hilo = idx >> 7;
        int r = idx & 127;
        int m = r >> 1, half = r & 1;
        int mg = bm + m; if (mg >= M) mg = M - 1;
        char* dst = stg + (hilo ? OFF_AL : OFF_AH) + half * 1024 + m * 16;
        const __nv_bfloat16* src = (hilo ? d_h1lo : d_h1hi) + (size_t)mg * K + k0 + half * 8;
        cp16(dst, src);
    }
}

__global__ void __launch_bounds__(128) k_mma(int K, int which, int M,
                                             const float* __restrict__ gw,
                                             const float* __restrict__ gb) {
    __shared__ __align__(16) char stage[2 * STAGE_BYTES];
    __shared__ __align__(16) float Ssh[64 * 36];
    int t = threadIdx.x;
    int lane = t & 31, wrp = t >> 5;
    int bm = blockIdx.x * 64;
    const __nv_bfloat16* gBhi = which ? d_b2hi : d_b1hi;
    const __nv_bfloat16* gBlo = which ? d_b2lo : d_b1lo;
    float* C = which ? d_t2 : d_t1;

    if (which == 0) {
        for (int i = t; i < 512; i += 128) {
            int row = i >> 3, q = i & 7;
            int g = bm + row;
            float4 v = (g < M) ? ((const float4*)d_snode)[g * 8 + q]
                               : make_float4(0.f, 0.f, 0.f, 0.f);
            *(float4*)&Ssh[row * 36 + q * 4] = v;
        }
    }
    __syncthreads();

    const int NC = K >> 4;

    // prologue: fill stage 0 (chunk 0)
    load_b(stage, gBhi, gBlo, K, 0, t);
    if (which) load_a(stage, K, 0, t, bm, M);
    asm volatile("cp.async.commit_group;" ::: "memory");
    if (!which) gen_a(stage, Ssh, gw, gb, 0, t);
    asm volatile("cp.async.wait_group 0;" ::: "memory");
    __syncthreads();

    float acc[16][4];
#pragma unroll
    for (int nt = 0; nt < 16; nt++) {
        acc[nt][0] = 0.f; acc[nt][1] = 0.f; acc[nt][2] = 0.f; acc[nt][3] = 0.f;
    }

    uint32_t l15 = lane & 15;
    uint32_t aoff = (wrp * 16 + l15) * 16 + ((uint32_t)(lane >> 4) << 10);
    uint32_t boff = (l15 < 8) ? l15 * 48 : (l15 - 8) * 48 + 16;

    for (int c = 0; c < NC; c++) {
        int cur = c & 1;
        char* stg = stage + cur * STAGE_BYTES;
        if (c + 1 < NC) {
            char* nstg = stage + (cur ^ 1) * STAGE_BYTES;
            int nk0 = (c + 1) << 4;
            load_b(nstg, gBhi, gBlo, K, nk0, t);
            if (which) load_a(nstg, K, nk0, t, bm, M);
            asm volatile("cp.async.commit_group;" ::: "memory");
            if (!which) gen_a(nstg, Ssh, gw, gb, nk0, t);
        }
        uint32_t sb = (uint32_t)__cvta_generic_to_shared(stg);
        uint32_t ah[4], al[4];
        ldsm4(ah, sb + OFF_AH + aoff);
        ldsm4(al, sb + OFF_AL + aoff);
#pragma unroll
        for (int nt = 0; nt < 16; nt++) {
            uint32_t bh[2], bl[2];
            ldsm2(bh, sb + OFF_BH + nt * 384 + boff);
            ldsm2(bl, sb + OFF_BL + nt * 384 + boff);
            mma_bf16(acc[nt], ah, bh);
            mma_bf16(acc[nt], ah, bl);
            mma_bf16(acc[nt], al, bh);
        }
        if (c + 1 < NC)
            asm volatile("cp.async.wait_group 0;" ::: "memory");
        __syncthreads();
    }

    // epilogue: acc -> C (fp32)
    int mrow = bm + wrp * 16 + lane / 4;
    int nbase = (lane % 4) * 2;
#pragma unroll
    for (int nt = 0; nt < 16; nt++) {
        int n0 = nt * 8 + nbase;
        if (mrow < M)
            *(float2*)&C[(size_t)mrow * 128 + n0] = make_float2(acc[nt][0], acc[nt][1]);
        if (mrow + 8 < M)
            *(float2*)&C[(size_t)(mrow + 8) * 128 + n0] = make_float2(acc[nt][2], acc[nt][3]);
    }
}

// ---------------- GCN aggregation -------------------------------------------
// FIRST: out = gelu(dinv*sum+b) split to bf16 hi/lo (feeds GEMM2)
// !FIRST: out = dinv*sum+b as fp32 to ext_out (final)
template <bool FIRST>
__global__ void k_agg(const float* __restrict__ bias, float* __restrict__ ext_out) {
    const float* tin = FIRST ? d_t1 : d_t2;
    int node = blockIdx.x * 8 + (threadIdx.x >> 5);
    int lane = threadIdx.x & 31;
    if (node >= NN) return;
    int r0 = d_rowptr[node], r1 = d_rowptr[node + 1];
    float4 acc = make_float4(0.f, 0.f, 0.f, 0.f);
    const float4* t4 = (const float4*)tin;
    for (int i = r0; i < r1; i++) {
        int s = d_colsrc[i];
        float w = d_dinv[s];
        float4 v = t4[s * 32 + lane];
        acc.x += w * v.x; acc.y += w * v.y; acc.z += w * v.z; acc.w += w * v.w;
    }
    float dn = d_dinv[node];
    float4 b = ((const float4*)bias)[lane];
    float4 r;
    r.x = acc.x * dn + b.x;
    r.y = acc.y * dn + b.y;
    r.z = acc.z * dn + b.z;
    r.w = acc.w * dn + b.w;
    if (FIRST) {
        float vv[4];
        vv[0] = gelu_exact(r.x); vv[1] = gelu_exact(r.y);
        vv[2] = gelu_exact(r.z); vv[3] = gelu_exact(r.w);
        int base = node * DD + lane * 4;
#pragma unroll
        for (int c = 0; c < 4; c++) {
            __nv_bfloat16 h = __float2bfloat16(vv[c]);
            d_h1hi[base + c] = h;
            d_h1lo[base + c] = __float2bfloat16(vv[c] - __bfloat162float(h));
        }
    } else {
        ((float4*)ext_out)[node * 32 + lane] = r;
    }
}

// ---------------- launch -----------------------------------------------------
extern "C" void kernel_launch(void* const* d_in, const int* in_sizes, int n_in,
                              void* d_out, int out_size) {
    const float* x       = (const float*)d_in[0];
    const int*   eiw     = (const int*)d_in[1];      // words; dtype detected on device
    const float* gat_w   = (const float*)d_in[2];
    const float* att_src = (const float*)d_in[3];
    const float* att_dst = (const float*)d_in[4];
    const float* gat_b   = (const float*)d_in[5];
    const float* w1      = (const float*)d_in[6];
    const float* b1      = (const float*)d_in[7];
    const float* w2      = (const float*)d_in[8];
    const float* b2      = (const float*)d_in[9];
    float* out = (float*)d_out;

    k_setup<<<(NN + 255) / 256, 256>>>(eiw, gat_w, att_src, att_dst);
    k_prepB<<<(128 * HD + 128 * 128 + 255) / 256, 256>>>(w1, w2);
    k_count<<<(EE + 255) / 256, 256>>>(eiw);
    k_scan<<<1, 1024>>>();
    k_fillnode<<<(ET + 255) / 256, 256>>>(eiw, x);
    k_gat<<<(NN + 31) / 32, 256>>>(x);
    k_mma<<<(NN + 63) / 64, 128>>>(HD, 0, NN, gat_w, gat_b);
    k_agg<true><<<(NN + 7) / 8, 256>>>(b1, nullptr);
    k_mma<<<(NN + 63) / 64, 128>>>(DD, 1, NN, nullptr, nullptr);
    k_agg<false><<<(NN + 7) / 8, 256>>>(b2, out);
}